// round 10
// baseline (speedup 1.0000x reference)
#include <cuda_runtime.h>
#include <cuda_fp16.h>
#include <cstdint>

// Causal SDPA: B=2, H=16, S=2048, D=128, fp32 in/out.
// R10: split-operand warp mapping to halve smem crossbar traffic.
//   QK: warp (rg,h) computes S[32 rows][kv half h]  -> K read 2x not 4x
//   PV: warp (rg,h) computes O[32 rows][d half h]   -> V read 2x not 4x
//   softmax combined across the h-pair via smem partials + named barriers
//   fp16 m16n8k16 mma w/ f32 accum, ldmatrix, cp.async double buffering,
//   fused prologue (K->fp16, V->fp16 transposed). 2 independent CTAs/SM.

#define B_ 2
#define H_ 16
#define S_ 2048
#define D_ 128

constexpr int BR      = 64;
constexpr int BC      = 64;
constexpr int THREADS = 128;

// smem row strides in 32-bit words; stride % 32 == 4 -> ldmatrix phases
// cover all 32 banks (conflict-free).
constexpr int KSTW = 68;   // K tile row: 128 halfs + pad
constexpr int VSTW = 36;   // VT tile row: 64 halfs + pad
constexpr int PSTW = 36;   // P tile row:  64 halfs + pad

constexpr int KTILE_W = BC * KSTW;             // 4352 words / stage
constexpr int VTILE_W = D_ * VSTW;             // 4608 words / stage
constexpr int PTILE_W = BR * PSTW;             // 2304 words
constexpr int SM_K  = 0;
constexpr int SM_V  = 2 * KTILE_W;             // 8704
constexpr int SM_P  = SM_V + 2 * VTILE_W;      // 17920
constexpr int SM_ML = SM_P + PTILE_W;          // 20224 (mh[2][64], lh[2][64])
constexpr int SMEM_WORDS = SM_ML + 256;        // 20480
constexpr int SMEM_BYTES = SMEM_WORDS * 4;     // 81920 B -> 2 CTAs/SM

constexpr int KV_ELEMS = B_ * H_ * S_ * D_;

__device__ __align__(16) __half g_kth[KV_ELEMS];   // K fp16 [bh][s][d]
__device__ __align__(16) __half g_vth[KV_ELEMS];   // V fp16 transposed [bh][d][s]

// ---------------------------------------------------------------------------
// Fused prologue (unchanged from R8): V->fp16 transposed tile + K->fp16 slice.
// ---------------------------------------------------------------------------
__global__ void __launch_bounds__(256)
prep_kv_kernel(const float* __restrict__ v, const float4* __restrict__ k) {
    __shared__ __half tile[64][65];
    const int bh = blockIdx.z;
    const int s0 = blockIdx.x * 64;
    const int d0 = blockIdx.y * 64;
    const float* vp = v + (long)bh * S_ * D_;
    __half* vtp = g_vth + (long)bh * (long)D_ * S_;

    const int tx = threadIdx.x & 15;
    const int ty = threadIdx.x >> 4;
    #pragma unroll
    for (int p = 0; p < 4; ++p) {
        int si = ty + p * 16;
        float4 a = *(const float4*)(vp + (long)(s0 + si) * D_ + d0 + tx * 4);
        tile[si][tx * 4 + 0] = __float2half_rn(a.x);
        tile[si][tx * 4 + 1] = __float2half_rn(a.y);
        tile[si][tx * 4 + 2] = __float2half_rn(a.z);
        tile[si][tx * 4 + 3] = __float2half_rn(a.w);
    }
    {
        const long nblk = (long)gridDim.x * gridDim.y * gridDim.z;
        const long bid  = (long)(blockIdx.z * gridDim.y + blockIdx.y) * gridDim.x
                        + blockIdx.x;
        const long per  = (KV_ELEMS / 4) / nblk;
        uint2* kd = reinterpret_cast<uint2*>(g_kth);
        long i0 = bid * per;
        for (long i = i0 + threadIdx.x; i < i0 + per; i += 256) {
            float4 a = k[i];
            __half2 lo = __floats2half2_rn(a.x, a.y);
            __half2 hi = __floats2half2_rn(a.z, a.w);
            uint2 o;
            o.x = *(uint32_t*)&lo;
            o.y = *(uint32_t*)&hi;
            kd[i] = o;
        }
    }
    __syncthreads();
    const int lane = threadIdx.x & 31;
    const int w    = threadIdx.x >> 5;
    #pragma unroll
    for (int p = 0; p < 8; ++p) {
        int di = w + p * 8;
        __half2 h = __halves2half2(tile[2 * lane][di], tile[2 * lane + 1][di]);
        *(__half2*)(vtp + (long)(d0 + di) * S_ + s0 + 2 * lane) = h;
    }
}

// ---------------------------------------------------------------------------
__device__ __forceinline__ void mma_f16(float c[4],
                                        uint32_t a0, uint32_t a1, uint32_t a2, uint32_t a3,
                                        uint32_t b0, uint32_t b1) {
    asm volatile(
        "mma.sync.aligned.m16n8k16.row.col.f32.f16.f16.f32 "
        "{%0,%1,%2,%3}, {%4,%5,%6,%7}, {%8,%9}, {%0,%1,%2,%3};"
        : "+f"(c[0]), "+f"(c[1]), "+f"(c[2]), "+f"(c[3])
        : "r"(a0), "r"(a1), "r"(a2), "r"(a3), "r"(b0), "r"(b1));
}
__device__ __forceinline__ void ldsm4(uint32_t& r0, uint32_t& r1,
                                      uint32_t& r2, uint32_t& r3, uint32_t addr) {
    asm volatile("ldmatrix.sync.aligned.m8n8.x4.shared.b16 {%0,%1,%2,%3}, [%4];"
                 : "=r"(r0), "=r"(r1), "=r"(r2), "=r"(r3) : "r"(addr));
}
__device__ __forceinline__ void cp_async16(uint32_t dst, const void* src) {
    asm volatile("cp.async.cg.shared.global [%0], [%1], 16;" :: "r"(dst), "l"(src));
}
__device__ __forceinline__ uint32_t pack2(float a, float b) {
    __half2 h = __floats2half2_rn(a, b);
    return *(uint32_t*)&h;
}
__device__ __forceinline__ void pair_bar(int id) {
    asm volatile("bar.sync %0, %1;" :: "r"(id), "r"(64) : "memory");
}

// Load one K tile (BC x 128 halfs) + one VT tile (128 x BC halfs).
__device__ __forceinline__ void load_kv_tile(const __half* kg, const __half* vtg,
                                             uint32_t kdst, uint32_t vdst, int tid) {
    #pragma unroll
    for (int it = 0; it < (BC * 16) / THREADS; ++it) {
        int i = tid + it * THREADS;
        int row = i >> 4, ch = i & 15;
        cp_async16(kdst + (uint32_t)(row * KSTW + ch * 4) * 4u, kg + row * D_ + ch * 8);
    }
    #pragma unroll
    for (int it = 0; it < (D_ * 8) / THREADS; ++it) {
        int i = tid + it * THREADS;
        int row = i >> 3, ch = i & 7;
        cp_async16(vdst + (uint32_t)(row * VSTW + ch * 4) * 4u, vtg + (long)row * S_ + ch * 8);
    }
    asm volatile("cp.async.commit_group;");
}

__global__ __launch_bounds__(THREADS, 2)
void fa_split_kernel(const float* __restrict__ q, float* __restrict__ out) {
    extern __shared__ __align__(16) uint32_t smem[];
    float* mlf = (float*)(smem + SM_ML);   // [0..127]=mh[h][row], [128..255]=lh

    const int tid  = threadIdx.x;
    const int w    = tid >> 5;
    const int lane = tid & 31;
    const int g    = lane >> 2;
    const int c    = lane & 3;
    const int r8   = lane & 7;
    const int s3   = (lane >> 3) & 1;
    const int s4   = lane >> 4;
    const int rg   = w >> 1;    // row group (rows 32*rg .. +32)
    const int h    = w & 1;     // kv half (QK) / d half (PV)

    const int qt     = (int)(gridDim.x - 1) - (int)blockIdx.x;
    const int bh     = blockIdx.y;
    const long base  = (long)bh * S_ * D_;
    const int q_base = qt * BR;
    const int njt    = qt + 1;
    const int wrow   = q_base + rg * 32;
    const int rl0    = rg * 32 + g;          // local row id of first owned row

    const float scale = 0.08838834764831845f;

    const uint32_t smem_u32 = (uint32_t)__cvta_generic_to_shared(smem);
    const uint32_t k_u32 = smem_u32;
    const uint32_t v_u32 = smem_u32 + (uint32_t)SM_V * 4u;
    const uint32_t p_u32 = smem_u32 + (uint32_t)SM_P * 4u;

    const __half* kg  = g_kth + base;
    const __half* vtg = g_vth + base;

    load_kv_tile(kg, vtg, k_u32, v_u32, tid);

    // ---- Q a-frags: 2 row-blocks x 8 k-steps x 4 regs ----
    uint32_t qreg[2][8][4];
    {
        const float* qp = q + base;
        #pragma unroll
        for (int rb = 0; rb < 2; ++rb) {
            const long r0 = wrow + 16 * rb + g, r1 = r0 + 8;
            #pragma unroll
            for (int ks = 0; ks < 8; ++ks) {
                int col = ks * 16 + 2 * c;
                qreg[rb][ks][0] = pack2(qp[r0 * D_ + col]     * scale, qp[r0 * D_ + col + 1] * scale);
                qreg[rb][ks][1] = pack2(qp[r1 * D_ + col]     * scale, qp[r1 * D_ + col + 1] * scale);
                qreg[rb][ks][2] = pack2(qp[r0 * D_ + col + 8] * scale, qp[r0 * D_ + col + 9] * scale);
                qreg[rb][ks][3] = pack2(qp[r1 * D_ + col + 8] * scale, qp[r1 * D_ + col + 9] * scale);
            }
        }
    }

    float oacc[2][8][4];
    #pragma unroll
    for (int rb = 0; rb < 2; ++rb)
        #pragma unroll
        for (int nt = 0; nt < 8; ++nt)
            oacc[rb][nt][0] = oacc[rb][nt][1] = oacc[rb][nt][2] = oacc[rb][nt][3] = 0.f;
    float m[4] = {-1e30f, -1e30f, -1e30f, -1e30f};
    float l[4] = {0.f, 0.f, 0.f, 0.f};

    for (int j = 0; j < njt; ++j) {
        const int st = j & 1;
        if (j + 1 < njt) {
            const int ns = (j + 1) & 1;
            load_kv_tile(kg + (long)(j + 1) * BC * D_,
                         vtg + (j + 1) * BC,
                         k_u32 + (uint32_t)(ns * KTILE_W) * 4u,
                         v_u32 + (uint32_t)(ns * VTILE_W) * 4u, tid);
            asm volatile("cp.async.wait_group 1;");
        } else {
            asm volatile("cp.async.wait_group 0;");
        }
        __syncthreads();

        const int kvb = j * BC;

        // ---- S = Q K^T : 32 rows x 32 kv cols (this warp's half) ----
        float sacc[2][4][4];
        #pragma unroll
        for (int rb = 0; rb < 2; ++rb)
            #pragma unroll
            for (int nt = 0; nt < 4; ++nt)
                sacc[rb][nt][0] = sacc[rb][nt][1] = sacc[rb][nt][2] = sacc[rb][nt][3] = 0.f;

        const uint32_t ktb = k_u32 + (uint32_t)(st * KTILE_W) * 4u
                           + (uint32_t)((h * 32 + r8) * KSTW + s4 * 8 + s3 * 4) * 4u;
        #pragma unroll
        for (int nt = 0; nt < 4; ++nt) {
            const uint32_t krow = ktb + (uint32_t)(nt * 8 * KSTW) * 4u;
            #pragma unroll
            for (int kp = 0; kp < 4; ++kp) {
                uint32_t b0, b1, b2, b3;
                ldsm4(b0, b1, b2, b3, krow + (uint32_t)(kp * 16) * 4u);
                mma_f16(sacc[0][nt], qreg[0][2*kp][0], qreg[0][2*kp][1], qreg[0][2*kp][2], qreg[0][2*kp][3], b0, b1);
                mma_f16(sacc[1][nt], qreg[1][2*kp][0], qreg[1][2*kp][1], qreg[1][2*kp][2], qreg[1][2*kp][3], b0, b1);
                mma_f16(sacc[0][nt], qreg[0][2*kp+1][0], qreg[0][2*kp+1][1], qreg[0][2*kp+1][2], qreg[0][2*kp+1][3], b2, b3);
                mma_f16(sacc[1][nt], qreg[1][2*kp+1][0], qreg[1][2*kp+1][1], qreg[1][2*kp+1][2], qreg[1][2*kp+1][3], b2, b3);
            }
        }

        // ---- causal mask ----
        if (kvb + BC - 1 > wrow) {
            #pragma unroll
            for (int rb = 0; rb < 2; ++rb)
                #pragma unroll
                for (int nt = 0; nt < 4; ++nt)
                    #pragma unroll
                    for (int idx = 0; idx < 4; ++idx) {
                        int col = kvb + h * 32 + nt * 8 + (c << 1) + (idx & 1);
                        int row = wrow + 16 * rb + g + ((idx >> 1) << 3);
                        if (col > row) sacc[rb][nt][idx] = -1e30f;
                    }
        }

        // ---- partial row max over this half ----
        float tmx[4];
        #pragma unroll
        for (int rb = 0; rb < 2; ++rb) {
            float a0 = fmaxf(sacc[rb][0][0], sacc[rb][0][1]);
            float a1 = fmaxf(sacc[rb][0][2], sacc[rb][0][3]);
            #pragma unroll
            for (int nt = 1; nt < 4; ++nt) {
                a0 = fmaxf(a0, fmaxf(sacc[rb][nt][0], sacc[rb][nt][1]));
                a1 = fmaxf(a1, fmaxf(sacc[rb][nt][2], sacc[rb][nt][3]));
            }
            tmx[2 * rb]     = a0;
            tmx[2 * rb + 1] = a1;
        }
        #pragma unroll
        for (int r = 0; r < 4; ++r) {
            tmx[r] = fmaxf(tmx[r], __shfl_xor_sync(0xffffffffu, tmx[r], 1));
            tmx[r] = fmaxf(tmx[r], __shfl_xor_sync(0xffffffffu, tmx[r], 2));
        }
        if (c == 0) {
            mlf[h * 64 + rl0]      = tmx[0];
            mlf[h * 64 + rl0 + 8]  = tmx[1];
            mlf[h * 64 + rl0 + 16] = tmx[2];
            mlf[h * 64 + rl0 + 24] = tmx[3];
        }
        pair_bar(1 + rg);

        // ---- combined max, alpha ----
        float nm[4], alpha[4];
        #pragma unroll
        for (int r = 0; r < 4; ++r) {
            int rl = rl0 + r * 8;
            float tm = fmaxf(mlf[rl], mlf[64 + rl]);
            nm[r] = fmaxf(m[r], tm);
            alpha[r] = __expf(m[r] - nm[r]);
            m[r] = nm[r];
        }

        // ---- exp, partial sums, P -> smem (this half's 32 cols) ----
        float ts[4] = {0.f, 0.f, 0.f, 0.f};
        #pragma unroll
        for (int rb = 0; rb < 2; ++rb) {
            #pragma unroll
            for (int nt = 0; nt < 4; ++nt) {
                float p00 = __expf(sacc[rb][nt][0] - nm[2 * rb]);
                float p01 = __expf(sacc[rb][nt][1] - nm[2 * rb]);
                float p10 = __expf(sacc[rb][nt][2] - nm[2 * rb + 1]);
                float p11 = __expf(sacc[rb][nt][3] - nm[2 * rb + 1]);
                ts[2 * rb]     += p00 + p01;
                ts[2 * rb + 1] += p10 + p11;
                int wcol = h * 16 + nt * 4 + c;
                int prow = rg * 32 + 16 * rb + g;
                smem[SM_P + prow * PSTW + wcol]       = pack2(p00, p01);
                smem[SM_P + (prow + 8) * PSTW + wcol] = pack2(p10, p11);
            }
        }
        #pragma unroll
        for (int r = 0; r < 4; ++r) {
            ts[r] += __shfl_xor_sync(0xffffffffu, ts[r], 1);
            ts[r] += __shfl_xor_sync(0xffffffffu, ts[r], 2);
        }
        if (c == 0) {
            mlf[128 + h * 64 + rl0]      = ts[0];
            mlf[128 + h * 64 + rl0 + 8]  = ts[1];
            mlf[128 + h * 64 + rl0 + 16] = ts[2];
            mlf[128 + h * 64 + rl0 + 24] = ts[3];
        }
        pair_bar(1 + rg);

        #pragma unroll
        for (int r = 0; r < 4; ++r) {
            int rl = rl0 + r * 8;
            l[r] = l[r] * alpha[r] + mlf[128 + rl] + mlf[128 + 64 + rl];
        }
        #pragma unroll
        for (int rb = 0; rb < 2; ++rb)
            #pragma unroll
            for (int nt = 0; nt < 8; ++nt) {
                oacc[rb][nt][0] *= alpha[2 * rb];
                oacc[rb][nt][1] *= alpha[2 * rb];
                oacc[rb][nt][2] *= alpha[2 * rb + 1];
                oacc[rb][nt][3] *= alpha[2 * rb + 1];
            }

        // ---- O += P V : 32 rows x 64 d cols (this warp's half) ----
        uint32_t pa[2][4][4];
        #pragma unroll
        for (int rb = 0; rb < 2; ++rb)
            #pragma unroll
            for (int ks = 0; ks < 4; ++ks)
                ldsm4(pa[rb][ks][0], pa[rb][ks][1], pa[rb][ks][2], pa[rb][ks][3],
                      p_u32 + (uint32_t)((rg * 32 + 16 * rb + r8 + s3 * 8) * PSTW
                                         + ks * 8 + s4 * 4) * 4u);

        const uint32_t vtb = v_u32 + (uint32_t)(st * VTILE_W) * 4u
                           + (uint32_t)((h * 64 + r8) * VSTW + s4 * 8 + s3 * 4) * 4u;
        #pragma unroll
        for (int nt = 0; nt < 8; ++nt) {
            const uint32_t vrow = vtb + (uint32_t)(nt * 8 * VSTW) * 4u;
            uint32_t b0, b1, b2, b3, b4, b5, b6, b7;
            ldsm4(b0, b1, b2, b3, vrow);
            ldsm4(b4, b5, b6, b7, vrow + 64u);
            #pragma unroll
            for (int rb = 0; rb < 2; ++rb) {
                mma_f16(oacc[rb][nt], pa[rb][0][0], pa[rb][0][1], pa[rb][0][2], pa[rb][0][3], b0, b1);
                mma_f16(oacc[rb][nt], pa[rb][1][0], pa[rb][1][1], pa[rb][1][2], pa[rb][1][3], b2, b3);
                mma_f16(oacc[rb][nt], pa[rb][2][0], pa[rb][2][1], pa[rb][2][2], pa[rb][2][3], b4, b5);
                mma_f16(oacc[rb][nt], pa[rb][3][0], pa[rb][3][1], pa[rb][3][2], pa[rb][3][3], b6, b7);
            }
        }

        __syncthreads();
    }

    // ---- epilogue: normalize and store (rows of rg, d cols of half h) ----
    float inv[4];
    #pragma unroll
    for (int r = 0; r < 4; ++r) inv[r] = 1.f / l[r];
    float* op = out + base;
    #pragma unroll
    for (int rb = 0; rb < 2; ++rb) {
        const long r0 = wrow + 16 * rb + g, r1 = r0 + 8;
        #pragma unroll
        for (int nt = 0; nt < 8; ++nt) {
            int dcol = h * 64 + nt * 8 + (c << 1);
            float2 o0 = make_float2(oacc[rb][nt][0] * inv[2 * rb],
                                    oacc[rb][nt][1] * inv[2 * rb]);
            float2 o1 = make_float2(oacc[rb][nt][2] * inv[2 * rb + 1],
                                    oacc[rb][nt][3] * inv[2 * rb + 1]);
            *(float2*)(op + r0 * D_ + dcol) = o0;
            *(float2*)(op + r1 * D_ + dcol) = o1;
        }
    }
}

extern "C" void kernel_launch(void* const* d_in, const int* in_sizes, int n_in,
                              void* d_out, int out_size) {
    const float* q = (const float*)d_in[0];
    const float* k = (const float*)d_in[1];
    const float* v = (const float*)d_in[2];
    float* out = (float*)d_out;

    dim3 pgrid(S_ / 64, D_ / 64, B_ * H_);
    prep_kv_kernel<<<pgrid, 256>>>(v, (const float4*)k);

    cudaFuncSetAttribute(fa_split_kernel,
                         cudaFuncAttributeMaxDynamicSharedMemorySize, SMEM_BYTES);
    dim3 grid(S_ / BR, B_ * H_);
    fa_split_kernel<<<grid, THREADS, SMEM_BYTES>>>(q, out);
}